// round 1
// baseline (speedup 1.0000x reference)
#include <cuda_runtime.h>

// ============================================================================
// VAE forward, fully fused, fp32 with packed fma.rn.f32x2 (sm_100a).
//
// Per CTA: 128 rows of the batch.
//   Phase 1: h = tanh(x @ W_in_e^T + b)        GEMM [128,784]x[784,50->pad64]
//   Phase 2: mu/ls -> z -> hd = tanh(...)      small per-row GEMMs in smem
//   Phase 3: out = (hd@Wmu^T+b) + exp(0.5(hd@Wls^T+b))*eps_x
//            GEMM [128,100]x[100,784], 25 column chunks of 32
// All intermediates live in shared memory; B-operands are stored duplicated
// as float2 so the packed FFMA2 multiplier loads directly with LDS.128.
// ============================================================================

#define NTHREADS 256
#define BM       128
#define IMG      784
#define HE       50
#define ZD       25
#define HDIM     100

#define KC1      98     // K-chunk for encoder GEMM (784 = 8*98)
#define NCH1     8
#define N1P      64     // padded N for encoder GEMM (50 -> 64)
#define A1_PITCH 132    // padded row pitch (banks) for x tile, 16B-friendly

#define BN3      32     // decoder column chunk
#define NCH3     25     // ceil(784/32)
#define W3PITCH  34     // padded float2 pitch for decoder W tiles

// ---- shared memory byte offsets (phases reuse regions; syncs separate) ----
#define OFF_A1   0       // [KC1][A1_PITCH] float  = 98*132*4 = 51744
#define OFF_W1   51744   // [KC1][N1P] float2(dup) = 98*64*8  = 50176 -> 101920
#define OFF_HS   0       // [128][HS_PITCH] float  = 128*52*4 = 26624
#define HS_PITCH 52
#define OFF_SWMU 26624   // W_mu_e 25x50 = 1250 floats
#define OFF_SWLS 31624   // W_ls_e 1250 floats
#define OFF_SBMU 36624   // b_mu_e 25
#define OFF_SBLS 36724   // b_ls_e 25
#define OFF_SWD  36824   // W_in_d 100x25 = 2500 floats
#define OFF_SBD  46824   // b_in_d 100 -> ends 47224
#define OFF_ZS   47232   // [128][ZS_PITCH] float = 128*26*4 = 13312 -> 60544
#define ZS_PITCH 26
#define OFF_HD   60544   // hd_s [100][128] float = 51200 -> 111744
#define OFF_WM3  0       // [100][W3PITCH] float2(dup) = 100*34*8 = 27200
#define OFF_WL3  27200   //                              -> 54400 (< OFF_HD, ok)
#define SMEM_BYTES 111744

typedef unsigned long long ull;

__device__ __forceinline__ void ffma2(ull& d, ull a, ull b) {
    // packed 2-lane fp32 fma: d = a*b + d  (lanewise)
    asm("fma.rn.f32x2 %0, %1, %2, %0;" : "+l"(d) : "l"(a), "l"(b));
}
__device__ __forceinline__ float2 unpack2(ull v) {
    float2 f;
    asm("mov.b64 {%0, %1}, %2;" : "=f"(f.x), "=f"(f.y) : "l"(v));
    return f;
}

__global__ void __launch_bounds__(NTHREADS, 2)
vae_fused(const float* __restrict__ x, const float* __restrict__ eps_z,
          const float* __restrict__ eps_x,
          const float* __restrict__ W_in_e, const float* __restrict__ b_in_e,
          const float* __restrict__ W_mu_e, const float* __restrict__ b_mu_e,
          const float* __restrict__ W_ls_e, const float* __restrict__ b_ls_e,
          const float* __restrict__ W_in_d, const float* __restrict__ b_in_d,
          const float* __restrict__ W_mu_d, const float* __restrict__ b_mu_d,
          const float* __restrict__ W_ls_d, const float* __restrict__ b_ls_d,
          float* __restrict__ out)
{
    extern __shared__ char smem[];
    const int t    = threadIdx.x;
    const int row0 = blockIdx.x * BM;

    // ===================== Phase 1: h = tanh(x @ W_in_e^T + b) ==============
    {
        float*  A1 = (float*)(smem + OFF_A1);   // A1[k*A1_PITCH + row] = x[row][k0+k]
        float2* W1 = (float2*)(smem + OFF_W1);  // W1[k*N1P + col] = dup(W_in_e[col][k0+k])
        const int tx = t & 15, ty = t >> 4;
        const int c0 = tx * 4, r0 = ty * 8;     // 4 cols, 8 rows (4 row-pairs)

        ull acc[4][4];
        #pragma unroll
        for (int p = 0; p < 4; p++) {
            #pragma unroll
            for (int c = 0; c < 4; c++) acc[p][c] = 0ull;
        }

        for (int ch = 0; ch < NCH1; ch++) {
            const int k0 = ch * KC1;
            __syncthreads();
            // stage x tile (coalesced float2 reads, transposed into A1)
            for (int e = t; e < BM * (KC1 / 2); e += NTHREADS) {
                int row = e / (KC1 / 2);
                int kk  = (e - row * (KC1 / 2)) * 2;
                float2 v = *(const float2*)(x + (size_t)(row0 + row) * IMG + k0 + kk);
                A1[kk * A1_PITCH + row]       = v.x;
                A1[(kk + 1) * A1_PITCH + row] = v.y;
            }
            // stage W tile, duplicated + zero-padded cols 50..63
            for (int e = t; e < KC1 * N1P; e += NTHREADS) {
                int col = e / KC1;
                int k   = e - col * KC1;
                float v = (col < HE) ? W_in_e[col * IMG + k0 + k] : 0.f;
                W1[k * N1P + col] = make_float2(v, v);
            }
            __syncthreads();
            #pragma unroll 14
            for (int k = 0; k < KC1; k++) {
                ulonglong2 a0 = *(const ulonglong2*)(A1 + k * A1_PITCH + r0);
                ulonglong2 a1 = *(const ulonglong2*)(A1 + k * A1_PITCH + r0 + 4);
                ulonglong2 b0 = *(const ulonglong2*)(W1 + k * N1P + c0);
                ulonglong2 b1 = *(const ulonglong2*)(W1 + k * N1P + c0 + 2);
                ffma2(acc[0][0], a0.x, b0.x); ffma2(acc[0][1], a0.x, b0.y);
                ffma2(acc[0][2], a0.x, b1.x); ffma2(acc[0][3], a0.x, b1.y);
                ffma2(acc[1][0], a0.y, b0.x); ffma2(acc[1][1], a0.y, b0.y);
                ffma2(acc[1][2], a0.y, b1.x); ffma2(acc[1][3], a0.y, b1.y);
                ffma2(acc[2][0], a1.x, b0.x); ffma2(acc[2][1], a1.x, b0.y);
                ffma2(acc[2][2], a1.x, b1.x); ffma2(acc[2][3], a1.x, b1.y);
                ffma2(acc[3][0], a1.y, b0.x); ffma2(acc[3][1], a1.y, b0.y);
                ffma2(acc[3][2], a1.y, b1.x); ffma2(acc[3][3], a1.y, b1.y);
            }
        }
        __syncthreads();  // A1/W1 region now dead; becomes h_s / small weights

        float* h_s = (float*)(smem + OFF_HS);
        #pragma unroll
        for (int c = 0; c < 4; c++) {
            int col = c0 + c;
            if (col < HE) {
                float bias = b_in_e[col];
                #pragma unroll
                for (int p = 0; p < 4; p++) {
                    float2 v = unpack2(acc[p][c]);
                    h_s[(r0 + 2 * p) * HS_PITCH + col]     = tanhf(v.x + bias);
                    h_s[(r0 + 2 * p + 1) * HS_PITCH + col] = tanhf(v.y + bias);
                }
            }
        }
        // load small weights (region disjoint from h_s)
        float* sWmu = (float*)(smem + OFF_SWMU);
        float* sWls = (float*)(smem + OFF_SWLS);
        float* sWd  = (float*)(smem + OFF_SWD);
        for (int e = t; e < ZD * HE; e += NTHREADS) { sWmu[e] = W_mu_e[e]; sWls[e] = W_ls_e[e]; }
        for (int e = t; e < HDIM * ZD; e += NTHREADS) sWd[e] = W_in_d[e];
        if (t < ZD)   { ((float*)(smem + OFF_SBMU))[t] = b_mu_e[t];
                        ((float*)(smem + OFF_SBLS))[t] = b_ls_e[t]; }
        if (t < HDIM) { ((float*)(smem + OFF_SBD))[t]  = b_in_d[t]; }
    }
    __syncthreads();

    // ===================== Phase 2: mu/ls -> z -> hd =========================
    {
        const int r    = t >> 1;
        const int half = t & 1;
        const int rg   = row0 + r;
        const int jbase = half ? 13 : 0;
        const int nj    = half ? 12 : 13;
        const float* h_r  = (float*)(smem + OFF_HS) + r * HS_PITCH;
        const float* sWmu = (float*)(smem + OFF_SWMU);
        const float* sWls = (float*)(smem + OFF_SWLS);
        const float* sbmu = (float*)(smem + OFF_SBMU);
        const float* sbls = (float*)(smem + OFF_SBLS);

        float accm[13], accl[13];
        #pragma unroll
        for (int jj = 0; jj < 13; jj++) { accm[jj] = 0.f; accl[jj] = 0.f; }
        for (int k = 0; k < HE; k++) {
            float hv = h_r[k];
            #pragma unroll
            for (int jj = 0; jj < 13; jj++) {
                if (jj < nj) {
                    accm[jj] += hv * sWmu[(jbase + jj) * HE + k];
                    accl[jj] += hv * sWls[(jbase + jj) * HE + k];
                }
            }
        }
        float* z_s = (float*)(smem + OFF_ZS);
        #pragma unroll
        for (int jj = 0; jj < 13; jj++) {
            if (jj < nj) {
                int j = jbase + jj;
                float m = accm[jj] + sbmu[j];
                float l = accl[jj] + sbls[j];
                z_s[r * ZS_PITCH + j] = m + __expf(0.5f * l) * eps_z[(size_t)rg * ZD + j];
            }
        }
        __syncthreads();

        float zr[ZD];
        #pragma unroll
        for (int k = 0; k < ZD; k++) zr[k] = z_s[r * ZS_PITCH + k];
        float* hd_s = (float*)(smem + OFF_HD);
        const float* sWd = (float*)(smem + OFF_SWD);
        const float* sbd = (float*)(smem + OFF_SBD);
        for (int i = 0; i < HDIM / 2; i++) {
            int jd = half * (HDIM / 2) + i;
            float acc = sbd[jd];
            #pragma unroll
            for (int k = 0; k < ZD; k++) acc += zr[k] * sWd[jd * ZD + k];
            hd_s[jd * BM + r] = tanhf(acc);
        }
    }

    // ===================== Phase 3: decoder GEMMs + epilogue =================
    {
        const int tx3 = t & 7, ty3 = t >> 3;
        const int c0 = tx3 * 4, r0 = ty3 * 4;   // 4 cols, 4 rows (2 row-pairs)
        float2* Wm3 = (float2*)(smem + OFF_WM3);
        float2* Wl3 = (float2*)(smem + OFF_WL3);
        const float* hd_s = (float*)(smem + OFF_HD);

        for (int cb = 0; cb < NCH3; cb++) {
            const int gc0 = cb * BN3;
            __syncthreads();   // protect W tiles (and hd_s on first iter)
            for (int e = t; e < HDIM * BN3; e += NTHREADS) {
                int col  = e / HDIM;
                int k    = e - col * HDIM;
                int gcol = gc0 + col;
                float vm = 0.f, vl = 0.f;
                if (gcol < IMG) {
                    vm = W_mu_d[gcol * HDIM + k];
                    vl = W_ls_d[gcol * HDIM + k];
                }
                Wm3[k * W3PITCH + col] = make_float2(vm, vm);
                Wl3[k * W3PITCH + col] = make_float2(vl, vl);
            }
            __syncthreads();

            ull am[2][4], al[2][4];
            #pragma unroll
            for (int p = 0; p < 2; p++) {
                #pragma unroll
                for (int c = 0; c < 4; c++) { am[p][c] = 0ull; al[p][c] = 0ull; }
            }
            #pragma unroll 10
            for (int k = 0; k < HDIM; k++) {
                ulonglong2 a   = *(const ulonglong2*)(hd_s + k * BM + r0);
                ulonglong2 bm0 = *(const ulonglong2*)(Wm3 + k * W3PITCH + c0);
                ulonglong2 bm1 = *(const ulonglong2*)(Wm3 + k * W3PITCH + c0 + 2);
                ulonglong2 bl0 = *(const ulonglong2*)(Wl3 + k * W3PITCH + c0);
                ulonglong2 bl1 = *(const ulonglong2*)(Wl3 + k * W3PITCH + c0 + 2);
                ffma2(am[0][0], a.x, bm0.x); ffma2(am[0][1], a.x, bm0.y);
                ffma2(am[0][2], a.x, bm1.x); ffma2(am[0][3], a.x, bm1.y);
                ffma2(am[1][0], a.y, bm0.x); ffma2(am[1][1], a.y, bm0.y);
                ffma2(am[1][2], a.y, bm1.x); ffma2(am[1][3], a.y, bm1.y);
                ffma2(al[0][0], a.x, bl0.x); ffma2(al[0][1], a.x, bl0.y);
                ffma2(al[0][2], a.x, bl1.x); ffma2(al[0][3], a.x, bl1.y);
                ffma2(al[1][0], a.y, bl0.x); ffma2(al[1][1], a.y, bl0.y);
                ffma2(al[1][2], a.y, bl1.x); ffma2(al[1][3], a.y, bl1.y);
            }

            const int gc = gc0 + c0;
            if (gc < IMG) {
                float4 bm4 = *(const float4*)(b_mu_d + gc);
                float4 bl4 = *(const float4*)(b_ls_d + gc);
                #pragma unroll
                for (int p = 0; p < 2; p++) {
                    float2 m[4], l[4];
                    #pragma unroll
                    for (int c = 0; c < 4; c++) { m[c] = unpack2(am[p][c]); l[c] = unpack2(al[p][c]); }
                    const size_t rA = (size_t)(row0 + r0 + 2 * p);
                    float4 eA = *(const float4*)(eps_x + rA * IMG + gc);
                    float4 eB = *(const float4*)(eps_x + (rA + 1) * IMG + gc);
                    float4 oA, oB;
                    oA.x = (m[0].x + bm4.x) + __expf(0.5f * (l[0].x + bl4.x)) * eA.x;
                    oA.y = (m[1].x + bm4.y) + __expf(0.5f * (l[1].x + bl4.y)) * eA.y;
                    oA.z = (m[2].x + bm4.z) + __expf(0.5f * (l[2].x + bl4.z)) * eA.z;
                    oA.w = (m[3].x + bm4.w) + __expf(0.5f * (l[3].x + bl4.w)) * eA.w;
                    oB.x = (m[0].y + bm4.x) + __expf(0.5f * (l[0].y + bl4.x)) * eB.x;
                    oB.y = (m[1].y + bm4.y) + __expf(0.5f * (l[1].y + bl4.y)) * eB.y;
                    oB.z = (m[2].y + bm4.z) + __expf(0.5f * (l[2].y + bl4.z)) * eB.z;
                    oB.w = (m[3].y + bm4.w) + __expf(0.5f * (l[3].y + bl4.w)) * eB.w;
                    *(float4*)(out + rA * IMG + gc)       = oA;
                    *(float4*)(out + (rA + 1) * IMG + gc) = oB;
                }
            }
        }
    }
}

extern "C" void kernel_launch(void* const* d_in, const int* in_sizes, int n_in,
                              void* d_out, int out_size) {
    const float* x      = (const float*)d_in[0];
    const float* eps_z  = (const float*)d_in[1];
    const float* eps_x  = (const float*)d_in[2];
    const float* W_in_e = (const float*)d_in[3];
    const float* b_in_e = (const float*)d_in[4];
    const float* W_mu_e = (const float*)d_in[5];
    const float* b_mu_e = (const float*)d_in[6];
    const float* W_ls_e = (const float*)d_in[7];
    const float* b_ls_e = (const float*)d_in[8];
    const float* W_in_d = (const float*)d_in[9];
    const float* b_in_d = (const float*)d_in[10];
    const float* W_mu_d = (const float*)d_in[11];
    const float* b_mu_d = (const float*)d_in[12];
    const float* W_ls_d = (const float*)d_in[13];
    const float* b_ls_d = (const float*)d_in[14];
    float* out = (float*)d_out;

    cudaFuncSetAttribute(vae_fused, cudaFuncAttributeMaxDynamicSharedMemorySize, SMEM_BYTES);
    int nrows = in_sizes[0] / IMG;      // 131072
    int grid  = nrows / BM;             // 1024
    vae_fused<<<grid, NTHREADS, SMEM_BYTES>>>(
        x, eps_z, eps_x, W_in_e, b_in_e, W_mu_e, b_mu_e, W_ls_e, b_ls_e,
        W_in_d, b_in_d, W_mu_d, b_mu_d, W_ls_d, b_ls_d, out);
}

// round 4
// speedup vs baseline: 1.0006x; 1.0006x over previous
#include <cuda_runtime.h>

// ============================================================================
// VAE forward, fully fused, fp32 with packed fma.rn.f32x2 (sm_100a).
//
// Per CTA: 128 rows of the batch.
//   Phase 1: h = tanh(x @ W_in_e^T + b)        GEMM [128,784]x[784,50->pad64]
//   Phase 2: mu/ls -> z -> hd = tanh(...)      small per-row GEMMs in smem
//   Phase 3: out = (hd@Wmu^T+b) + exp(0.5(hd@Wls^T+b))*eps_x
//            GEMM [128,100]x[100,784], 25 column chunks of 32
// All intermediates live in shared memory; B-operands are stored duplicated
// as float2 so the packed FFMA2 multiplier loads directly with LDS.128.
// ============================================================================

#define NTHREADS 256
#define BM       128
#define IMG      784
#define HE       50
#define ZD       25
#define HDIM     100

#define KC1      98     // K-chunk for encoder GEMM (784 = 8*98)
#define NCH1     8
#define N1P      64     // padded N for encoder GEMM (50 -> 64)
#define A1_PITCH 132    // padded row pitch (banks) for x tile, 16B-friendly

#define BN3      32     // decoder column chunk
#define NCH3     25     // ceil(784/32)
#define W3PITCH  34     // padded float2 pitch for decoder W tiles

// ---- shared memory byte offsets (phases reuse regions; syncs separate) ----
#define OFF_A1   0       // [KC1][A1_PITCH] float  = 98*132*4 = 51744
#define OFF_W1   51744   // [KC1][N1P] float2(dup) = 98*64*8  = 50176 -> 101920
#define OFF_HS   0       // [128][HS_PITCH] float  = 128*52*4 = 26624
#define HS_PITCH 52
#define OFF_SWMU 26624   // W_mu_e 25x50 = 1250 floats
#define OFF_SWLS 31624   // W_ls_e 1250 floats
#define OFF_SBMU 36624   // b_mu_e 25
#define OFF_SBLS 36724   // b_ls_e 25
#define OFF_SWD  36824   // W_in_d 100x25 = 2500 floats
#define OFF_SBD  46824   // b_in_d 100 -> ends 47224
#define OFF_ZS   47232   // [128][ZS_PITCH] float = 128*26*4 = 13312 -> 60544
#define ZS_PITCH 26
#define OFF_HD   60544   // hd_s [100][128] float = 51200 -> 111744
#define OFF_WM3  0       // [100][W3PITCH] float2(dup) = 100*34*8 = 27200
#define OFF_WL3  27200   //                              -> 54400 (< OFF_HD, ok)
#define SMEM_BYTES 111744

typedef unsigned long long ull;

__device__ __forceinline__ void ffma2(ull& d, ull a, ull b) {
    // packed 2-lane fp32 fma: d = a*b + d  (lanewise)
    asm("fma.rn.f32x2 %0, %1, %2, %0;" : "+l"(d) : "l"(a), "l"(b));
}
__device__ __forceinline__ float2 unpack2(ull v) {
    float2 f;
    asm("mov.b64 {%0, %1}, %2;" : "=f"(f.x), "=f"(f.y) : "l"(v));
    return f;
}

__global__ void __launch_bounds__(NTHREADS, 2)
vae_fused(const float* __restrict__ x, const float* __restrict__ eps_z,
          const float* __restrict__ eps_x,
          const float* __restrict__ W_in_e, const float* __restrict__ b_in_e,
          const float* __restrict__ W_mu_e, const float* __restrict__ b_mu_e,
          const float* __restrict__ W_ls_e, const float* __restrict__ b_ls_e,
          const float* __restrict__ W_in_d, const float* __restrict__ b_in_d,
          const float* __restrict__ W_mu_d, const float* __restrict__ b_mu_d,
          const float* __restrict__ W_ls_d, const float* __restrict__ b_ls_d,
          float* __restrict__ out)
{
    extern __shared__ char smem[];
    const int t    = threadIdx.x;
    const int row0 = blockIdx.x * BM;

    // ===================== Phase 1: h = tanh(x @ W_in_e^T + b) ==============
    {
        float*  A1 = (float*)(smem + OFF_A1);   // A1[k*A1_PITCH + row] = x[row][k0+k]
        float2* W1 = (float2*)(smem + OFF_W1);  // W1[k*N1P + col] = dup(W_in_e[col][k0+k])
        const int tx = t & 15, ty = t >> 4;
        const int c0 = tx * 4, r0 = ty * 8;     // 4 cols, 8 rows (4 row-pairs)

        ull acc[4][4];
        #pragma unroll
        for (int p = 0; p < 4; p++) {
            #pragma unroll
            for (int c = 0; c < 4; c++) acc[p][c] = 0ull;
        }

        for (int ch = 0; ch < NCH1; ch++) {
            const int k0 = ch * KC1;
            __syncthreads();
            // stage x tile (coalesced float2 reads, transposed into A1)
            for (int e = t; e < BM * (KC1 / 2); e += NTHREADS) {
                int row = e / (KC1 / 2);
                int kk  = (e - row * (KC1 / 2)) * 2;
                float2 v = *(const float2*)(x + (size_t)(row0 + row) * IMG + k0 + kk);
                A1[kk * A1_PITCH + row]       = v.x;
                A1[(kk + 1) * A1_PITCH + row] = v.y;
            }
            // stage W tile, duplicated + zero-padded cols 50..63
            for (int e = t; e < KC1 * N1P; e += NTHREADS) {
                int col = e / KC1;
                int k   = e - col * KC1;
                float v = (col < HE) ? W_in_e[col * IMG + k0 + k] : 0.f;
                W1[k * N1P + col] = make_float2(v, v);
            }
            __syncthreads();
            #pragma unroll 14
            for (int k = 0; k < KC1; k++) {
                ulonglong2 a0 = *(const ulonglong2*)(A1 + k * A1_PITCH + r0);
                ulonglong2 a1 = *(const ulonglong2*)(A1 + k * A1_PITCH + r0 + 4);
                ulonglong2 b0 = *(const ulonglong2*)(W1 + k * N1P + c0);
                ulonglong2 b1 = *(const ulonglong2*)(W1 + k * N1P + c0 + 2);
                ffma2(acc[0][0], a0.x, b0.x); ffma2(acc[0][1], a0.x, b0.y);
                ffma2(acc[0][2], a0.x, b1.x); ffma2(acc[0][3], a0.x, b1.y);
                ffma2(acc[1][0], a0.y, b0.x); ffma2(acc[1][1], a0.y, b0.y);
                ffma2(acc[1][2], a0.y, b1.x); ffma2(acc[1][3], a0.y, b1.y);
                ffma2(acc[2][0], a1.x, b0.x); ffma2(acc[2][1], a1.x, b0.y);
                ffma2(acc[2][2], a1.x, b1.x); ffma2(acc[2][3], a1.x, b1.y);
                ffma2(acc[3][0], a1.y, b0.x); ffma2(acc[3][1], a1.y, b0.y);
                ffma2(acc[3][2], a1.y, b1.x); ffma2(acc[3][3], a1.y, b1.y);
            }
        }
        __syncthreads();  // A1/W1 region now dead; becomes h_s / small weights

        float* h_s = (float*)(smem + OFF_HS);
        #pragma unroll
        for (int c = 0; c < 4; c++) {
            int col = c0 + c;
            if (col < HE) {
                float bias = b_in_e[col];
                #pragma unroll
                for (int p = 0; p < 4; p++) {
                    float2 v = unpack2(acc[p][c]);
                    h_s[(r0 + 2 * p) * HS_PITCH + col]     = tanhf(v.x + bias);
                    h_s[(r0 + 2 * p + 1) * HS_PITCH + col] = tanhf(v.y + bias);
                }
            }
        }
        // load small weights (region disjoint from h_s)
        float* sWmu = (float*)(smem + OFF_SWMU);
        float* sWls = (float*)(smem + OFF_SWLS);
        float* sWd  = (float*)(smem + OFF_SWD);
        for (int e = t; e < ZD * HE; e += NTHREADS) { sWmu[e] = W_mu_e[e]; sWls[e] = W_ls_e[e]; }
        for (int e = t; e < HDIM * ZD; e += NTHREADS) sWd[e] = W_in_d[e];
        if (t < ZD)   { ((float*)(smem + OFF_SBMU))[t] = b_mu_e[t];
                        ((float*)(smem + OFF_SBLS))[t] = b_ls_e[t]; }
        if (t < HDIM) { ((float*)(smem + OFF_SBD))[t]  = b_in_d[t]; }
    }
    __syncthreads();

    // ===================== Phase 2: mu/ls -> z -> hd =========================
    {
        const int r    = t >> 1;
        const int half = t & 1;
        const int rg   = row0 + r;
        const int jbase = half ? 13 : 0;
        const int nj    = half ? 12 : 13;
        const float* h_r  = (float*)(smem + OFF_HS) + r * HS_PITCH;
        const float* sWmu = (float*)(smem + OFF_SWMU);
        const float* sWls = (float*)(smem + OFF_SWLS);
        const float* sbmu = (float*)(smem + OFF_SBMU);
        const float* sbls = (float*)(smem + OFF_SBLS);

        float accm[13], accl[13];
        #pragma unroll
        for (int jj = 0; jj < 13; jj++) { accm[jj] = 0.f; accl[jj] = 0.f; }
        for (int k = 0; k < HE; k++) {
            float hv = h_r[k];
            #pragma unroll
            for (int jj = 0; jj < 13; jj++) {
                if (jj < nj) {
                    accm[jj] += hv * sWmu[(jbase + jj) * HE + k];
                    accl[jj] += hv * sWls[(jbase + jj) * HE + k];
                }
            }
        }
        float* z_s = (float*)(smem + OFF_ZS);
        #pragma unroll
        for (int jj = 0; jj < 13; jj++) {
            if (jj < nj) {
                int j = jbase + jj;
                float m = accm[jj] + sbmu[j];
                float l = accl[jj] + sbls[j];
                z_s[r * ZS_PITCH + j] = m + __expf(0.5f * l) * eps_z[(size_t)rg * ZD + j];
            }
        }
        __syncthreads();

        float zr[ZD];
        #pragma unroll
        for (int k = 0; k < ZD; k++) zr[k] = z_s[r * ZS_PITCH + k];
        float* hd_s = (float*)(smem + OFF_HD);
        const float* sWd = (float*)(smem + OFF_SWD);
        const float* sbd = (float*)(smem + OFF_SBD);
        for (int i = 0; i < HDIM / 2; i++) {
            int jd = half * (HDIM / 2) + i;
            float acc = sbd[jd];
            #pragma unroll
            for (int k = 0; k < ZD; k++) acc += zr[k] * sWd[jd * ZD + k];
            hd_s[jd * BM + r] = tanhf(acc);
        }
    }

    // ===================== Phase 3: decoder GEMMs + epilogue =================
    {
        const int tx3 = t & 7, ty3 = t >> 3;
        const int c0 = tx3 * 4, r0 = ty3 * 4;   // 4 cols, 4 rows (2 row-pairs)
        float2* Wm3 = (float2*)(smem + OFF_WM3);
        float2* Wl3 = (float2*)(smem + OFF_WL3);
        const float* hd_s = (float*)(smem + OFF_HD);

        for (int cb = 0; cb < NCH3; cb++) {
            const int gc0 = cb * BN3;
            __syncthreads();   // protect W tiles (and hd_s on first iter)
            for (int e = t; e < HDIM * BN3; e += NTHREADS) {
                int col  = e / HDIM;
                int k    = e - col * HDIM;
                int gcol = gc0 + col;
                float vm = 0.f, vl = 0.f;
                if (gcol < IMG) {
                    vm = W_mu_d[gcol * HDIM + k];
                    vl = W_ls_d[gcol * HDIM + k];
                }
                Wm3[k * W3PITCH + col] = make_float2(vm, vm);
                Wl3[k * W3PITCH + col] = make_float2(vl, vl);
            }
            __syncthreads();

            ull am[2][4], al[2][4];
            #pragma unroll
            for (int p = 0; p < 2; p++) {
                #pragma unroll
                for (int c = 0; c < 4; c++) { am[p][c] = 0ull; al[p][c] = 0ull; }
            }
            #pragma unroll 10
            for (int k = 0; k < HDIM; k++) {
                ulonglong2 a   = *(const ulonglong2*)(hd_s + k * BM + r0);
                ulonglong2 bm0 = *(const ulonglong2*)(Wm3 + k * W3PITCH + c0);
                ulonglong2 bm1 = *(const ulonglong2*)(Wm3 + k * W3PITCH + c0 + 2);
                ulonglong2 bl0 = *(const ulonglong2*)(Wl3 + k * W3PITCH + c0);
                ulonglong2 bl1 = *(const ulonglong2*)(Wl3 + k * W3PITCH + c0 + 2);
                ffma2(am[0][0], a.x, bm0.x); ffma2(am[0][1], a.x, bm0.y);
                ffma2(am[0][2], a.x, bm1.x); ffma2(am[0][3], a.x, bm1.y);
                ffma2(am[1][0], a.y, bm0.x); ffma2(am[1][1], a.y, bm0.y);
                ffma2(am[1][2], a.y, bm1.x); ffma2(am[1][3], a.y, bm1.y);
                ffma2(al[0][0], a.x, bl0.x); ffma2(al[0][1], a.x, bl0.y);
                ffma2(al[0][2], a.x, bl1.x); ffma2(al[0][3], a.x, bl1.y);
                ffma2(al[1][0], a.y, bl0.x); ffma2(al[1][1], a.y, bl0.y);
                ffma2(al[1][2], a.y, bl1.x); ffma2(al[1][3], a.y, bl1.y);
            }

            const int gc = gc0 + c0;
            if (gc < IMG) {
                float4 bm4 = *(const float4*)(b_mu_d + gc);
                float4 bl4 = *(const float4*)(b_ls_d + gc);
                #pragma unroll
                for (int p = 0; p < 2; p++) {
                    float2 m[4], l[4];
                    #pragma unroll
                    for (int c = 0; c < 4; c++) { m[c] = unpack2(am[p][c]); l[c] = unpack2(al[p][c]); }
                    const size_t rA = (size_t)(row0 + r0 + 2 * p);
                    float4 eA = *(const float4*)(eps_x + rA * IMG + gc);
                    float4 eB = *(const float4*)(eps_x + (rA + 1) * IMG + gc);
                    float4 oA, oB;
                    oA.x = (m[0].x + bm4.x) + __expf(0.5f * (l[0].x + bl4.x)) * eA.x;
                    oA.y = (m[1].x + bm4.y) + __expf(0.5f * (l[1].x + bl4.y)) * eA.y;
                    oA.z = (m[2].x + bm4.z) + __expf(0.5f * (l[2].x + bl4.z)) * eA.z;
                    oA.w = (m[3].x + bm4.w) + __expf(0.5f * (l[3].x + bl4.w)) * eA.w;
                    oB.x = (m[0].y + bm4.x) + __expf(0.5f * (l[0].y + bl4.x)) * eB.x;
                    oB.y = (m[1].y + bm4.y) + __expf(0.5f * (l[1].y + bl4.y)) * eB.y;
                    oB.z = (m[2].y + bm4.z) + __expf(0.5f * (l[2].y + bl4.z)) * eB.z;
                    oB.w = (m[3].y + bm4.w) + __expf(0.5f * (l[3].y + bl4.w)) * eB.w;
                    *(float4*)(out + rA * IMG + gc)       = oA;
                    *(float4*)(out + (rA + 1) * IMG + gc) = oB;
                }
            }
        }
    }
}

extern "C" void kernel_launch(void* const* d_in, const int* in_sizes, int n_in,
                              void* d_out, int out_size) {
    const float* x      = (const float*)d_in[0];
    const float* eps_z  = (const float*)d_in[1];
    const float* eps_x  = (const float*)d_in[2];
    const float* W_in_e = (const float*)d_in[3];
    const float* b_in_e = (const float*)d_in[4];
    const float* W_mu_e = (const float*)d_in[5];
    const float* b_mu_e = (const float*)d_in[6];
    const float* W_ls_e = (const float*)d_in[7];
    const float* b_ls_e = (const float*)d_in[8];
    const float* W_in_d = (const float*)d_in[9];
    const float* b_in_d = (const float*)d_in[10];
    const float* W_mu_d = (const float*)d_in[11];
    const float* b_mu_d = (const float*)d_in[12];
    const float* W_ls_d = (const float*)d_in[13];
    const float* b_ls_d = (const float*)d_in[14];
    float* out = (float*)d_out;

    cudaFuncSetAttribute(vae_fused, cudaFuncAttributeMaxDynamicSharedMemorySize, SMEM_BYTES);
    int nrows = in_sizes[0] / IMG;      // 131072
    int grid  = nrows / BM;             // 1024
    vae_fused<<<grid, NTHREADS, SMEM_BYTES>>>(
        x, eps_z, eps_x, W_in_e, b_in_e, W_mu_e, b_mu_e, W_ls_e, b_ls_e,
        W_in_d, b_in_d, W_mu_d, b_mu_d, W_ls_d, b_ls_d, out);
}